// round 8
// baseline (speedup 1.0000x reference)
#include <cuda_runtime.h>
#include <math.h>
#include <stdint.h>

#define Bn 512
#define Tn 256
#define Cn 384
#define Hn 64

// Scratch for projected q/k/v (allocation-free).
__device__ float g_q[(size_t)Bn * Tn * Hn];
__device__ float g_k[(size_t)Bn * Tn * Hn];
__device__ float g_v[(size_t)Bn * Tn * Hn];

__device__ __forceinline__ uint32_t smem_u32(const void* p) {
    uint32_t a;
    asm("{ .reg .u64 t; cvta.to.shared.u64 t, %1; cvt.u32.u64 %0, t; }"
        : "=r"(a) : "l"(p));
    return a;
}
__device__ __forceinline__ uint32_t to_tf32(float f) {
    uint32_t u;
    asm("cvt.rna.tf32.f32 %0, %1;" : "=r"(u) : "f"(f));
    return u;
}
__device__ __forceinline__ void mma_tf32(float c[4], const uint32_t a[4],
                                         const uint32_t b[2]) {
    asm volatile(
        "mma.sync.aligned.m16n8k8.row.col.f32.tf32.tf32.f32 "
        "{%0,%1,%2,%3}, {%4,%5,%6,%7}, {%8,%9}, {%0,%1,%2,%3};\n"
        : "+f"(c[0]), "+f"(c[1]), "+f"(c[2]), "+f"(c[3])
        : "r"(a[0]), "r"(a[1]), "r"(a[2]), "r"(a[3]), "r"(b[0]), "r"(b[1]));
}
#define CP_ASYNC16(dst, src) \
    asm volatile("cp.async.cg.shared.global [%0], [%1], 16;" :: "r"(dst), "l"(src))
#define CP_COMMIT() asm volatile("cp.async.commit_group;" ::: "memory")
#define CP_WAIT(N)  asm volatile("cp.async.wait_group %0;" :: "n"(N) : "memory")

// ---------------------------------------------------------------------------
// Projection: tf32 mma.sync + double-buffered cp.async (unchanged, ~152us).
// ---------------------------------------------------------------------------
#define A_LD 36
#define B_LD 200
#define STAGE_FL (128 * A_LD + 32 * B_LD)
#define P_SMEM_BYTES (2 * STAGE_FL * 4)
#define ST_LD 68

__device__ __forceinline__ void proj_issue(
    const float* __restrict__ x, const float* __restrict__ Wk,
    const float* __restrict__ Wq, const float* __restrict__ Wv,
    float* As, float* Bs, int tid, size_t row0, int k0)
{
#pragma unroll
    for (int j = 0; j < 4; j++) {
        int idx = tid + j * 256;
        int r = idx >> 3, c4 = idx & 7;
        CP_ASYNC16(smem_u32(&As[r * A_LD + c4 * 4]),
                   &x[(row0 + r) * Cn + k0 + c4 * 4]);
    }
#pragma unroll
    for (int nt = 0; nt < 3; nt++) {
        const float* W = (nt == 0) ? Wk : (nt == 1) ? Wq : Wv;
#pragma unroll
        for (int j = 0; j < 2; j++) {
            int idx = tid + j * 256;
            int k = idx >> 4, n4 = idx & 15;
            CP_ASYNC16(smem_u32(&Bs[k * B_LD + nt * 64 + n4 * 4]),
                       &W[(k0 + k) * Hn + n4 * 4]);
        }
    }
}

__global__ __launch_bounds__(256) void proj_mma_kernel(
    const float* __restrict__ x,
    const float* __restrict__ Wk,
    const float* __restrict__ Wq,
    const float* __restrict__ Wv)
{
    extern __shared__ float smp[];

    const int tid   = threadIdx.x;
    const int wid   = tid >> 5;
    const int lane  = tid & 31;
    const int gid   = lane >> 2;
    const int tig   = lane & 3;
    const int warpM = wid >> 2;
    const int warpN = wid & 3;
    const size_t row0 = (size_t)blockIdx.x * 128;

    float acc[4][6][4];
#pragma unroll
    for (int mi = 0; mi < 4; mi++)
#pragma unroll
        for (int ni = 0; ni < 6; ni++)
#pragma unroll
            for (int e = 0; e < 4; e++) acc[mi][ni][e] = 0.f;

    proj_issue(x, Wk, Wq, Wv, smp, smp + 128 * A_LD, tid, row0, 0);
    CP_COMMIT();

    for (int kt = 0; kt < Cn / 32; kt++) {
        const int buf = kt & 1;
        float* As = smp + buf * STAGE_FL;
        float* Bs = As + 128 * A_LD;

        if (kt + 1 < Cn / 32) {
            float* As2 = smp + (buf ^ 1) * STAGE_FL;
            proj_issue(x, Wk, Wq, Wv, As2, As2 + 128 * A_LD, tid, row0,
                       (kt + 1) * 32);
            CP_COMMIT();
            CP_WAIT(1);
        } else {
            CP_WAIT(0);
        }
        __syncthreads();

#pragma unroll
        for (int ks = 0; ks < 4; ks++) {
            const int kk = ks * 8;
            uint32_t afr[4][4];
#pragma unroll
            for (int mi = 0; mi < 4; mi++) {
                int m = warpM * 64 + mi * 16;
                afr[mi][0] = to_tf32(As[(m + gid) * A_LD + kk + tig]);
                afr[mi][1] = to_tf32(As[(m + gid + 8) * A_LD + kk + tig]);
                afr[mi][2] = to_tf32(As[(m + gid) * A_LD + kk + tig + 4]);
                afr[mi][3] = to_tf32(As[(m + gid + 8) * A_LD + kk + tig + 4]);
            }
            uint32_t bfr[6][2];
#pragma unroll
            for (int ni = 0; ni < 6; ni++) {
                int n = warpN * 48 + ni * 8;
                bfr[ni][0] = to_tf32(Bs[(kk + tig) * B_LD + n + gid]);
                bfr[ni][1] = to_tf32(Bs[(kk + tig + 4) * B_LD + n + gid]);
            }
#pragma unroll
            for (int mi = 0; mi < 4; mi++)
#pragma unroll
                for (int ni = 0; ni < 6; ni++)
                    mma_tf32(acc[mi][ni], afr[mi], bfr[ni]);
        }
        __syncthreads();
    }

    float* st = smp;
#pragma unroll
    for (int nt = 0; nt < 3; nt++) {
#pragma unroll
        for (int mi = 0; mi < 4; mi++)
#pragma unroll
            for (int ni = 0; ni < 6; ni++) {
                int nb = warpN * 48 + ni * 8;
                if ((nb >> 6) != nt) continue;
                int nloc = nb - nt * 64 + 2 * tig;
                int m = warpM * 64 + mi * 16 + gid;
                st[m * ST_LD + nloc]           = acc[mi][ni][0];
                st[m * ST_LD + nloc + 1]       = acc[mi][ni][1];
                st[(m + 8) * ST_LD + nloc]     = acc[mi][ni][2];
                st[(m + 8) * ST_LD + nloc + 1] = acc[mi][ni][3];
            }
        __syncthreads();
        float* dst = (nt == 0) ? g_k : (nt == 1) ? g_q : g_v;
#pragma unroll
        for (int j = 0; j < 8; j++) {
            int idx = tid + j * 256;
            int r = idx >> 4, c4 = idx & 15;
            float4 v = *reinterpret_cast<const float4*>(&st[r * ST_LD + c4 * 4]);
            *reinterpret_cast<float4*>(&dst[(row0 + r) * Hn + c4 * 4]) = v;
        }
        __syncthreads();
    }
}

// ---------------------------------------------------------------------------
// Attention v3: flash tf32 mma.sync, warp M-tile 32, CTA Q-tile 128.
// Block = (qt in {0,1}, b). 128 thr / 4 warps; warp w owns rows w*32..w*32+31.
// Per-warp diag chunk cd = 2*qt + (w>>1); chunks > cd skipped (compute only).
// smem: qs[128][68] + ks[64][68] + vs[64][72] + ps[4][32][68] = 105KB -> 2 CTA/SM.
// ---------------------------------------------------------------------------
#define QS_LD 68
#define KS_LD 68
#define VS_LD 72
#define PS_LD 68
#define AT_QS 0
#define AT_KS (128 * QS_LD)                 // 8704
#define AT_VS (AT_KS + 64 * KS_LD)          // 13056
#define AT_PS (AT_VS + 64 * VS_LD)          // 17664
#define AT_FLOATS (AT_PS + 4 * 32 * PS_LD)  // 26368 floats = 105472 B

__global__ __launch_bounds__(128, 2) void attn_mma_kernel(float* __restrict__ out)
{
    extern __shared__ float sm2[];
    float* qs = sm2 + AT_QS;
    float* ks = sm2 + AT_KS;
    float* vs = sm2 + AT_VS;

    const int tid  = threadIdx.x;
    const int w    = tid >> 5;
    const int lane = tid & 31;
    const int gid  = lane >> 2;
    const int tig  = lane & 3;
    float* psw = sm2 + AT_PS + w * 32 * PS_LD;

    const int qt = blockIdx.x;              // 0..1 (128-row q tiles)
    const int b  = blockIdx.y;
    const float scale = rsqrtf((float)Cn);
    const size_t base = (size_t)b * Tn * Hn;

    // Stage Q tile [128][64], scaled + tf32.
    {
        const size_t qb = base + (size_t)qt * 128 * Hn;
#pragma unroll
        for (int it = 0; it < 16; it++) {
            int idx = tid + it * 128;
            int r = idx >> 4, h4 = idx & 15;
            float4 v = *reinterpret_cast<const float4*>(&g_q[qb + (size_t)r * Hn + h4 * 4]);
            uint4 u = make_uint4(to_tf32(v.x * scale), to_tf32(v.y * scale),
                                 to_tf32(v.z * scale), to_tf32(v.w * scale));
            *reinterpret_cast<uint4*>(&qs[r * QS_LD + h4 * 4]) = u;
        }
    }

    float o[2][8][4];
#pragma unroll
    for (int mi = 0; mi < 2; mi++)
#pragma unroll
        for (int nt = 0; nt < 8; nt++)
#pragma unroll
            for (int e = 0; e < 4; e++) o[mi][nt][e] = 0.f;
    float mrun[2][2] = {{-INFINITY, -INFINITY}, {-INFINITY, -INFINITY}};
    float lrun[2][2] = {{0.f, 0.f}, {0.f, 0.f}};

    const int cd   = qt * 2 + (w >> 1);     // this warp's diagonal chunk
    const int nch  = qt * 2 + 2;            // chunks covering this q tile
    const int moff = 32 * (w & 1);          // row offset within diag chunk

    for (int c = 0; c < nch; c++) {
        __syncthreads();   // prior chunk fully consumed (and q staged, 1st iter)
        const size_t kb = base + (size_t)c * 64 * Hn;
#pragma unroll
        for (int it = 0; it < 8; it++) {
            int idx = tid + it * 128;
            int r = idx >> 4, h4 = idx & 15;
            float4 kv4 = *reinterpret_cast<const float4*>(&g_k[kb + (size_t)r * Hn + h4 * 4]);
            *reinterpret_cast<uint4*>(&ks[r * KS_LD + h4 * 4]) =
                make_uint4(to_tf32(kv4.x), to_tf32(kv4.y), to_tf32(kv4.z), to_tf32(kv4.w));
            float4 vv4 = *reinterpret_cast<const float4*>(&g_v[kb + (size_t)r * Hn + h4 * 4]);
            *reinterpret_cast<uint4*>(&vs[r * VS_LD + h4 * 4]) =
                make_uint4(to_tf32(vv4.x), to_tf32(vv4.y), to_tf32(vv4.z), to_tf32(vv4.w));
        }
        __syncthreads();
        if (c > cd) continue;   // fully-future chunk for this warp

        // ---- S = q . k^T : 8 ksteps x (2 mi x 8 nt) m16n8k8 ----
        float sacc[2][8][4];
#pragma unroll
        for (int mi = 0; mi < 2; mi++)
#pragma unroll
            for (int nt = 0; nt < 8; nt++)
#pragma unroll
                for (int e = 0; e < 4; e++) sacc[mi][nt][e] = 0.f;

#pragma unroll
        for (int kst = 0; kst < 8; kst++) {
            const int kk = kst * 8;
            uint32_t a[2][4];
#pragma unroll
            for (int mi = 0; mi < 2; mi++) {
                int m = w * 32 + mi * 16;
                a[mi][0] = __float_as_uint(qs[(m + gid) * QS_LD + kk + tig]);
                a[mi][1] = __float_as_uint(qs[(m + gid + 8) * QS_LD + kk + tig]);
                a[mi][2] = __float_as_uint(qs[(m + gid) * QS_LD + kk + tig + 4]);
                a[mi][3] = __float_as_uint(qs[(m + gid + 8) * QS_LD + kk + tig + 4]);
            }
#pragma unroll
            for (int nt = 0; nt < 8; nt++) {
                uint32_t bb[2];
                bb[0] = __float_as_uint(ks[(nt * 8 + gid) * KS_LD + kk + tig]);
                bb[1] = __float_as_uint(ks[(nt * 8 + gid) * KS_LD + kk + tig + 4]);
                mma_tf32(sacc[0][nt], a[0], bb);
                mma_tf32(sacc[1][nt], a[1], bb);
            }
        }

        // ---- mask (diag chunk) + online softmax + P store ----
        const bool diag = (c == cd);
#pragma unroll
        for (int mi = 0; mi < 2; mi++) {
            const int rl0 = moff + mi * 16 + gid;
            const int rl1 = rl0 + 8;
            float cm0 = -INFINITY, cm1 = -INFINITY;
#pragma unroll
            for (int nt = 0; nt < 8; nt++)
#pragma unroll
                for (int e = 0; e < 2; e++) {
                    int col = nt * 8 + 2 * tig + e;
                    if (diag && col > rl0) sacc[mi][nt][e]     = -INFINITY;
                    if (diag && col > rl1) sacc[mi][nt][2 + e] = -INFINITY;
                    cm0 = fmaxf(cm0, sacc[mi][nt][e]);
                    cm1 = fmaxf(cm1, sacc[mi][nt][2 + e]);
                }
            cm0 = fmaxf(cm0, __shfl_xor_sync(0xffffffffu, cm0, 1));
            cm0 = fmaxf(cm0, __shfl_xor_sync(0xffffffffu, cm0, 2));
            cm1 = fmaxf(cm1, __shfl_xor_sync(0xffffffffu, cm1, 1));
            cm1 = fmaxf(cm1, __shfl_xor_sync(0xffffffffu, cm1, 2));

            const float mn0 = fmaxf(mrun[mi][0], cm0);
            const float mn1 = fmaxf(mrun[mi][1], cm1);
            const float al0 = __expf(mrun[mi][0] - mn0);
            const float al1 = __expf(mrun[mi][1] - mn1);
            mrun[mi][0] = mn0; mrun[mi][1] = mn1;

            float sum0 = 0.f, sum1 = 0.f;
#pragma unroll
            for (int nt = 0; nt < 8; nt++)
#pragma unroll
                for (int e = 0; e < 2; e++) {
                    float p0 = __expf(sacc[mi][nt][e] - mn0);
                    float p1 = __expf(sacc[mi][nt][2 + e] - mn1);
                    sacc[mi][nt][e] = p0; sacc[mi][nt][2 + e] = p1;
                    sum0 += p0; sum1 += p1;
                }
            sum0 += __shfl_xor_sync(0xffffffffu, sum0, 1);
            sum0 += __shfl_xor_sync(0xffffffffu, sum0, 2);
            sum1 += __shfl_xor_sync(0xffffffffu, sum1, 1);
            sum1 += __shfl_xor_sync(0xffffffffu, sum1, 2);
            lrun[mi][0] = lrun[mi][0] * al0 + sum0;
            lrun[mi][1] = lrun[mi][1] * al1 + sum1;

#pragma unroll
            for (int nt = 0; nt < 8; nt++) {
                o[mi][nt][0] *= al0; o[mi][nt][1] *= al0;
                o[mi][nt][2] *= al1; o[mi][nt][3] *= al1;
            }

#pragma unroll
            for (int nt = 0; nt < 8; nt++) {
                float2 p0 = make_float2(__uint_as_float(to_tf32(sacc[mi][nt][0])),
                                        __uint_as_float(to_tf32(sacc[mi][nt][1])));
                *reinterpret_cast<float2*>(&psw[(mi * 16 + gid) * PS_LD + nt * 8 + 2 * tig]) = p0;
                float2 p1 = make_float2(__uint_as_float(to_tf32(sacc[mi][nt][2])),
                                        __uint_as_float(to_tf32(sacc[mi][nt][3])));
                *reinterpret_cast<float2*>(&psw[(mi * 16 + gid + 8) * PS_LD + nt * 8 + 2 * tig]) = p1;
            }
        }
        __syncwarp();

        // ---- O += P @ V : 8 ksteps x (2 mi x 8 nt) ----
#pragma unroll
        for (int kst = 0; kst < 8; kst++) {
            const int kk = kst * 8;
            uint32_t a[2][4];
#pragma unroll
            for (int mi = 0; mi < 2; mi++) {
                int m = mi * 16;
                a[mi][0] = __float_as_uint(psw[(m + gid) * PS_LD + kk + tig]);
                a[mi][1] = __float_as_uint(psw[(m + gid + 8) * PS_LD + kk + tig]);
                a[mi][2] = __float_as_uint(psw[(m + gid) * PS_LD + kk + tig + 4]);
                a[mi][3] = __float_as_uint(psw[(m + gid + 8) * PS_LD + kk + tig + 4]);
            }
#pragma unroll
            for (int nt = 0; nt < 8; nt++) {
                uint32_t bb[2];
                bb[0] = __float_as_uint(vs[(kk + tig) * VS_LD + nt * 8 + gid]);
                bb[1] = __float_as_uint(vs[(kk + tig + 4) * VS_LD + nt * 8 + gid]);
                mma_tf32(o[0][nt], a[0], bb);
                mma_tf32(o[1][nt], a[1], bb);
            }
        }
    }

    // Epilogue: normalize and store.
    const size_t ob = ((size_t)b * Tn + (size_t)qt * 128) * Hn;
#pragma unroll
    for (int mi = 0; mi < 2; mi++) {
        const float li0 = 1.0f / lrun[mi][0];
        const float li1 = 1.0f / lrun[mi][1];
        const int r0 = w * 32 + mi * 16 + gid;
#pragma unroll
        for (int nt = 0; nt < 8; nt++) {
            float2 v0 = make_float2(o[mi][nt][0] * li0, o[mi][nt][1] * li0);
            *reinterpret_cast<float2*>(&out[ob + (size_t)r0 * Hn + nt * 8 + 2 * tig]) = v0;
            float2 v1 = make_float2(o[mi][nt][2] * li1, o[mi][nt][3] * li1);
            *reinterpret_cast<float2*>(&out[ob + (size_t)(r0 + 8) * Hn + nt * 8 + 2 * tig]) = v1;
        }
    }
}

extern "C" void kernel_launch(void* const* d_in, const int* in_sizes, int n_in,
                              void* d_out, int out_size)
{
    const float* x  = (const float*)d_in[0];
    const float* Wk = (const float*)d_in[1];
    const float* Wq = (const float*)d_in[2];
    const float* Wv = (const float*)d_in[3];
    float* out = (float*)d_out;

    cudaFuncSetAttribute(proj_mma_kernel,
                         cudaFuncAttributeMaxDynamicSharedMemorySize, P_SMEM_BYTES);
    cudaFuncSetAttribute(attn_mma_kernel,
                         cudaFuncAttributeMaxDynamicSharedMemorySize, AT_FLOATS * 4);

    proj_mma_kernel<<<(Bn * Tn) / 128, 256, P_SMEM_BYTES>>>(x, Wk, Wq, Wv);
    attn_mma_kernel<<<dim3(Tn / 128, Bn), 128, AT_FLOATS * 4>>>(out);
}